// round 1
// baseline (speedup 1.0000x reference)
#include <cuda_runtime.h>
#include <cuda_bf16.h>
#include <math.h>

#define B_ 64
#define S_ 256
#define H_ 1024
#define V_ 10000
#define GRU_BLOCKS 128
#define DIMS_PER_BLK (H_ / GRU_BLOCKS)   // 8
#define GRU_SMEM ((3 * DIMS_PER_BLK * H_ + H_) * 4)   // 24*1024 + 1024 floats = 102400 B

// ---------------- scratch (device globals; no allocation allowed) ----------------
__device__ float g_emb[B_ * H_];       // embedded inputs
__device__ float g_gi[B_ * 3 * H_];    // input-side gate preactivations (bias pre-init)
__device__ float g_h[2 * H_];          // double-buffered hidden state
__device__ float g_rnn[B_ * H_];       // rnn_output (unused downstream except via g_cat, kept for clarity)
__device__ float g_cat[B_ * 2 * H_];   // [rnn_output | context]
__device__ float g_ue[H_];             // W_attn[:, H:2H]^T @ v_attn
__device__ float g_scores[B_ * S_];    // scores, then softmax weights
__device__ float g_pre[B_ * H_];       // concat preactivation (bias pre-init); tanh applied lazily
__device__ unsigned g_bar;             // grid barrier counter

// ---------------- K_pre: init + embedding + u_e ----------------
__global__ void k_pre(const int* __restrict__ seq,
                      const float* __restrict__ last_hidden,
                      const float* __restrict__ emb_table,
                      const float* __restrict__ b_ih,
                      const float* __restrict__ b_concat,
                      const float* __restrict__ b_out,
                      const float* __restrict__ W_attn,
                      const float* __restrict__ v_attn,
                      float* __restrict__ out)
{
    int blk = blockIdx.x, t = threadIdx.x;
    if (blk < 64) {
        int b = blk;
        int row = seq[b];
        for (int i = t; i < H_; i += 256) g_emb[b * H_ + i] = emb_table[row * H_ + i];
        for (int i = t; i < 3 * H_; i += 256) g_gi[b * 3 * H_ + i] = b_ih[i];
        for (int i = t; i < H_; i += 256) g_pre[b * H_ + i] = b_concat[i];
        for (int i = t; i < V_; i += 256) out[b * V_ + i] = b_out[i];
    } else if (blk < 68) {
        // u_e[k] = sum_h v_attn[h] * W_attn[h][H_ + k]
        int k = (blk - 64) * 256 + t;
        float acc = 0.f;
        for (int h = 0; h < H_; h++) acc += v_attn[h] * W_attn[h * 2 * H_ + H_ + k];
        g_ue[k] = acc;
    } else {
        for (int i = t; i < H_; i += 256) g_h[i] = last_hidden[i];
        if (t == 0) g_bar = 0u;
    }
}

// ---------------- generic tiled GEMM: C[b][r] += sum_k W[r][k]*E[b][k] ----------------
// MODE 0: gi      (E=g_emb ldE=1024, C=g_gi  ldC=3072, no tanh)
// MODE 1: concat  (E=g_cat ldE=2048, C=g_pre ldC=1024, no tanh)
// MODE 2: out     (E=tanh(g_pre) ldE=1024, C=Cout ldC=10000)
template<int R, int TR, int TC, int MODE>
__global__ void __launch_bounds__(256) k_gemm(const float* __restrict__ W, int lda,
                                              int Rtot, int Ksplit,
                                              float* __restrict__ Cout)
{
    constexpr int KC = 32;
    constexpr int NC = 64 / TC;  // 16
    const float* E; int ldE; float* C; int ldC;
    if constexpr (MODE == 0) { E = g_emb; ldE = H_;     C = g_gi;  ldC = 3 * H_; }
    else if constexpr (MODE == 1) { E = g_cat; ldE = 2 * H_; C = g_pre; ldC = H_; }
    else { E = g_pre; ldE = H_; C = Cout; ldC = V_; }

    __shared__ float sW[R][KC + 1];
    __shared__ float sE[KC][64 + 2];
    const int r0 = blockIdx.x * R;
    const int k0 = blockIdx.y * Ksplit;
    const int tcol = threadIdx.x % NC;
    const int trow = threadIdx.x / NC;

    float acc[TR][TC];
#pragma unroll
    for (int i = 0; i < TR; i++)
#pragma unroll
        for (int j = 0; j < TC; j++) acc[i][j] = 0.f;

    for (int kc = k0; kc < k0 + Ksplit; kc += KC) {
#pragma unroll
        for (int idx = threadIdx.x; idx < R * KC; idx += 256) {
            int rr = idx / KC, kk = idx % KC;
            int gr = r0 + rr;
            sW[rr][kk] = (gr < Rtot) ? W[(size_t)gr * lda + kc + kk] : 0.f;
        }
#pragma unroll
        for (int idx = threadIdx.x; idx < 64 * KC; idx += 256) {
            int bb = idx / KC, kk = idx % KC;
            float v = E[bb * ldE + kc + kk];
            if constexpr (MODE == 2) v = tanhf(v);
            sE[kk][bb] = v;
        }
        __syncthreads();
#pragma unroll 8
        for (int kk = 0; kk < KC; kk++) {
            float a[TR], bv[TC];
#pragma unroll
            for (int i = 0; i < TR; i++) a[i] = sW[trow * TR + i][kk];
#pragma unroll
            for (int j = 0; j < TC; j++) bv[j] = sE[kk][tcol * TC + j];
#pragma unroll
            for (int i = 0; i < TR; i++)
#pragma unroll
                for (int j = 0; j < TC; j++) acc[i][j] = fmaf(a[i], bv[j], acc[i][j]);
        }
        __syncthreads();
    }
#pragma unroll
    for (int i = 0; i < TR; i++) {
        int gr = r0 + trow * TR + i;
        if (gr < Rtot) {
#pragma unroll
            for (int j = 0; j < TC; j++)
                atomicAdd(&C[(size_t)(tcol * TC + j) * ldC + gr], acc[i][j]);
        }
    }
}

// ---------------- persistent GRU recurrence ----------------
__global__ void __launch_bounds__(256) k_gru(const float* __restrict__ W_hh,
                                             const float* __restrict__ b_hh,
                                             float* __restrict__ out)
{
    extern __shared__ float sm[];
    float* sW = sm;                     // 24 rows x 1024
    float* sH = sm + 3 * DIMS_PER_BLK * H_;

    const int t = threadIdx.x;
    const int j0 = blockIdx.x * DIMS_PER_BLK;

    // load this block's W_hh slice into SMEM once (rows: j..j+7, 1024+j.., 2048+j..)
    for (int idx = t; idx < 3 * DIMS_PER_BLK * H_; idx += 256) {
        int lr = idx >> 10;             // 0..23
        int h = idx & (H_ - 1);
        int g = lr >> 3, jj = lr & 7;
        sW[idx] = W_hh[(size_t)(g * H_ + j0 + jj) * H_ + h];
    }
    __syncthreads();

    const int w = t >> 5, lane = t & 31;
    const int j = j0 + w;
    const float bhr = b_hh[j];
    const float bhz = b_hh[H_ + j];
    const float bhn = b_hh[2 * H_ + j];
    const float* wr = sW + (w) * H_;
    const float* wz = sW + (8 + w) * H_;
    const float* wn = sW + (16 + w) * H_;
    const unsigned nb = gridDim.x;

    for (int b = 0; b < B_; b++) {
        // stage h into SMEM (double buffered in global)
        const float* hsrc = g_h + (b & 1) * H_;
        for (int i = t; i < H_; i += 256) sH[i] = hsrc[i];
        __syncthreads();

        // prefetch gi for this step early (independent of the dot)
        const float* gib = g_gi + b * 3 * H_;
        float gir = gib[j], giz = gib[H_ + j], gin = gib[2 * H_ + j];

        float ar = 0.f, az = 0.f, an = 0.f;
#pragma unroll
        for (int i = 0; i < 32; i++) {
            int hh = lane + i * 32;
            float hv = sH[hh];
            ar = fmaf(wr[hh], hv, ar);
            az = fmaf(wz[hh], hv, az);
            an = fmaf(wn[hh], hv, an);
        }
#pragma unroll
        for (int off = 16; off; off >>= 1) {
            ar += __shfl_down_sync(0xffffffffu, ar, off);
            az += __shfl_down_sync(0xffffffffu, az, off);
            an += __shfl_down_sync(0xffffffffu, an, off);
        }
        if (lane == 0) {
            float r = 1.f / (1.f + expf(-(gir + ar + bhr)));
            float z = 1.f / (1.f + expf(-(giz + az + bhz)));
            float n = tanhf(gin + r * (an + bhn));
            float hp = sH[j];
            float hn = (1.f - z) * n + z * hp;
            g_h[((b + 1) & 1) * H_ + j] = hn;
            g_rnn[b * H_ + j] = hn;
            g_cat[b * 2 * H_ + j] = hn;
            if (b == B_ - 1) out[B_ * V_ + j] = hn;   // hidden output
            __threadfence();                           // release this writer's stores
        }
        // grid barrier
        __syncthreads();
        if (t == 0) {
            atomicAdd(&g_bar, 1u);
            unsigned target = (unsigned)(b + 1) * nb;
            volatile unsigned* vb = &g_bar;
            while (*vb < target) __nanosleep(64);
            __threadfence();                           // acquire
        }
        __syncthreads();
    }
}

// ---------------- attention scores: scores[b][s] = enc[s][b][:] . u_e ----------------
__global__ void __launch_bounds__(256) k_scores(const float* __restrict__ enc)
{
    __shared__ float su[H_];
    for (int i = threadIdx.x; i < H_; i += 256) su[i] = g_ue[i];
    __syncthreads();
    int w = threadIdx.x >> 5, lane = threadIdx.x & 31;
    int gw = blockIdx.x * 8 + w;      // 0..16383
    int b = gw >> 8, s = gw & 255;
    const float* p = enc + (size_t)s * (B_ * H_) + b * H_;
    float acc = 0.f;
#pragma unroll 8
    for (int i = lane; i < H_; i += 32) acc = fmaf(p[i], su[i], acc);
#pragma unroll
    for (int off = 16; off; off >>= 1) acc += __shfl_down_sync(0xffffffffu, acc, off);
    if (lane == 0) g_scores[b * S_ + s] = acc;
}

// ---------------- softmax over s (per b) ----------------
__global__ void __launch_bounds__(256) k_softmax(float* __restrict__ out)
{
    int b = blockIdx.x, t = threadIdx.x;
    float v = g_scores[b * S_ + t];
    __shared__ float red[256];
    red[t] = v; __syncthreads();
    for (int o = 128; o; o >>= 1) { if (t < o) red[t] = fmaxf(red[t], red[t + o]); __syncthreads(); }
    float m = red[0]; __syncthreads();
    float e = expf(v - m);
    red[t] = e; __syncthreads();
    for (int o = 128; o; o >>= 1) { if (t < o) red[t] += red[t + o]; __syncthreads(); }
    float wgt = e / red[0];
    g_scores[b * S_ + t] = wgt;
    out[B_ * V_ + H_ + b * S_ + t] = wgt;   // attn_weights output
}

// ---------------- context: ctx[b][h] = sum_s w[b][s] * enc[s][b][h] ----------------
__global__ void __launch_bounds__(256) k_context(const float* __restrict__ enc)
{
    int b = blockIdx.x >> 2;
    int hb = (blockIdx.x & 3) * 256;
    __shared__ float sw_[S_];
    sw_[threadIdx.x] = g_scores[b * S_ + threadIdx.x];
    __syncthreads();
    int h = hb + threadIdx.x;
    const float* p = enc + b * H_ + h;
    float a0 = 0.f, a1 = 0.f, a2 = 0.f, a3 = 0.f;
#pragma unroll 4
    for (int s = 0; s < S_; s += 4) {
        a0 = fmaf(sw_[s + 0], p[(size_t)(s + 0) * (B_ * H_)], a0);
        a1 = fmaf(sw_[s + 1], p[(size_t)(s + 1) * (B_ * H_)], a1);
        a2 = fmaf(sw_[s + 2], p[(size_t)(s + 2) * (B_ * H_)], a2);
        a3 = fmaf(sw_[s + 3], p[(size_t)(s + 3) * (B_ * H_)], a3);
    }
    g_cat[b * 2 * H_ + H_ + h] = (a0 + a1) + (a2 + a3);
}

extern "C" void kernel_launch(void* const* d_in, const int* in_sizes, int n_in,
                              void* d_out, int out_size)
{
    const int*   seq        = (const int*)d_in[0];
    const float* last_hidden= (const float*)d_in[1];
    const float* enc        = (const float*)d_in[2];
    const float* emb_table  = (const float*)d_in[3];
    const float* W_ih       = (const float*)d_in[4];
    const float* W_hh       = (const float*)d_in[5];
    const float* b_ih       = (const float*)d_in[6];
    const float* b_hh       = (const float*)d_in[7];
    const float* W_attn     = (const float*)d_in[8];
    /* b_attn d_in[9] unused: softmax is shift-invariant */
    const float* v_attn     = (const float*)d_in[10];
    const float* W_concat   = (const float*)d_in[11];
    /* b_concat */
    const float* b_concat   = (const float*)d_in[12];
    const float* W_out      = (const float*)d_in[13];
    const float* b_out      = (const float*)d_in[14];
    float* out = (float*)d_out;

    cudaFuncSetAttribute(k_gru, cudaFuncAttributeMaxDynamicSharedMemorySize, GRU_SMEM);

    // init + embedding + u_e (+ barrier reset, h0)
    k_pre<<<69, 256>>>(seq, last_hidden, emb_table, b_ih, b_concat, b_out, W_attn, v_attn, out);

    // gi = emb @ W_ih^T  (+b_ih pre-init), split-K=2
    k_gemm<64, 4, 4, 0><<<dim3(48, 2), 256>>>(W_ih, H_, 3 * H_, 512, nullptr);

    // attention (independent of GRU): scores -> softmax -> context
    k_scores<<<2048, 256>>>(enc);
    k_softmax<<<64, 256>>>(out);
    k_context<<<256, 256>>>(enc);

    // sequential GRU recurrence (persistent kernel, custom grid barrier)
    k_gru<<<GRU_BLOCKS, 256, GRU_SMEM>>>(W_hh, b_hh, out);

    // concat preactivation: g_pre += [rnn|ctx] @ W_concat^T  (split-K=4)
    k_gemm<32, 2, 4, 1><<<dim3(32, 4), 256>>>(W_concat, 2 * H_, H_, 512, nullptr);

    // logits: out += tanh(g_pre) @ W_out^T  (split-K=2, bias pre-init)
    k_gemm<64, 4, 4, 2><<<dim3(157, 2), 256>>>(W_out, H_, V_, 512, out);
}

// round 2
// speedup vs baseline: 1.5090x; 1.5090x over previous
#include <cuda_runtime.h>
#include <cuda_bf16.h>
#include <math.h>

#define B_ 64
#define S_ 256
#define H_ 1024
#define V_ 10000
#define GRU_BLOCKS 128

// ---------------- scratch (device globals; no allocation allowed) ----------------
__device__ float g_emb[B_ * H_];       // embedded inputs
__device__ float g_gi[B_ * 3 * H_];    // input-side gate preactivations (bias pre-init)
__device__ float g_h[2 * H_];          // double-buffered hidden state
__device__ float g_cat[B_ * 2 * H_];   // [rnn_output | context]
__device__ float g_ue[H_];             // W_attn[:, H:2H]^T @ v_attn
__device__ float g_scores[B_ * S_];    // scores, then softmax weights
__device__ float g_pre[B_ * H_];       // concat preactivation (bias pre-init)
__device__ float g_E[B_ * H_];         // tanh(g_pre), staged once
__device__ unsigned g_bar;             // grid barrier counter

// ---------------- packed f32x2 helpers ----------------
__device__ __forceinline__ unsigned long long pack2(float x, float y) {
    unsigned long long r;
    asm("mov.b64 %0, {%1, %2};" : "=l"(r) : "f"(x), "f"(y));
    return r;
}
__device__ __forceinline__ void fma2(unsigned long long& d, unsigned long long a, unsigned long long b) {
    asm("fma.rn.f32x2 %0, %1, %2, %0;" : "+l"(d) : "l"(a), "l"(b));
}
__device__ __forceinline__ float2 unpack2(unsigned long long v) {
    float2 r;
    asm("mov.b64 {%0, %1}, %2;" : "=f"(r.x), "=f"(r.y) : "l"(v));
    return r;
}

// ---------------- K_pre: init + embedding ----------------
__global__ void k_pre(const int* __restrict__ seq,
                      const float* __restrict__ last_hidden,
                      const float* __restrict__ emb_table,
                      const float* __restrict__ b_ih,
                      const float* __restrict__ b_concat,
                      const float* __restrict__ b_out,
                      float* __restrict__ out)
{
    int blk = blockIdx.x, t = threadIdx.x;
    if (blk < 64) {
        int b = blk;
        int row = seq[b];
        for (int i = t; i < H_; i += 256) g_emb[b * H_ + i] = emb_table[(size_t)row * H_ + i];
        for (int i = t; i < 3 * H_; i += 256) g_gi[b * 3 * H_ + i] = b_ih[i];
        for (int i = t; i < H_; i += 256) g_pre[b * H_ + i] = b_concat[i];
        for (int i = t; i < V_; i += 256) out[b * V_ + i] = b_out[i];
    } else {
        for (int i = t; i < H_; i += 256) { g_h[i] = last_hidden[i]; g_ue[i] = 0.f; }
        if (t == 0) g_bar = 0u;
    }
}

// ---------------- u_e[k] = sum_h v_attn[h] * W_attn[h][H_ + k]  (h-split + atomics) ----------------
__global__ void __launch_bounds__(256) k_ue(const float* __restrict__ W_attn,
                                            const float* __restrict__ v_attn)
{
    int kb = blockIdx.x & 3;          // 4 k blocks of 256
    int hb = blockIdx.x >> 2;         // 16 h blocks of 64
    int k = kb * 256 + threadIdx.x;
    int h0 = hb * 64;
    float acc = 0.f;
#pragma unroll 8
    for (int h = h0; h < h0 + 64; h++)
        acc = fmaf(v_attn[h], W_attn[(size_t)h * (2 * H_) + H_ + k], acc);
    atomicAdd(&g_ue[k], acc);
}

// ---------------- GEMM: C[b][r] += sum_k W[r][k]*E[b][k], 8x8 regs, fma.f32x2 ----------------
// MODE 0: gi      (E=g_emb ldE=1024, C=g_gi  ldC=3072)
// MODE 1: concat  (E=g_cat ldE=2048, C=g_pre ldC=1024)
// MODE 2: out     (E=g_E   ldE=1024, C=Cout  ldC=10000)
template<int MODE>
__global__ void __launch_bounds__(256) k_gemm(const float* __restrict__ W, int lda,
                                              int Rtot, int Ksplit,
                                              float* __restrict__ Cout)
{
    constexpr int R = 256, KC = 16;
    const float* E; int ldE; float* C; int ldC;
    if constexpr (MODE == 0) { E = g_emb; ldE = H_;     C = g_gi;  ldC = 3 * H_; }
    else if constexpr (MODE == 1) { E = g_cat; ldE = 2 * H_; C = g_pre; ldC = H_; }
    else { E = g_E; ldE = H_; C = Cout; ldC = V_; }

    __shared__ float sWT[KC][R + 4];     // transposed W tile: [k][row]
    __shared__ float sE[KC][64 + 4];     // [k][batch]

    const int r0 = blockIdx.x * R;
    const int k0 = blockIdx.y * Ksplit;
    const int tcol = threadIdx.x & 7;    // 8 batch groups of 8
    const int trow = threadIdx.x >> 3;   // 32 row groups of 8

    unsigned long long acc2[8][4];
#pragma unroll
    for (int i = 0; i < 8; i++)
#pragma unroll
        for (int j = 0; j < 4; j++) acc2[i][j] = 0ull;

    for (int kc = k0; kc < k0 + Ksplit; kc += KC) {
        // stage W tile (256 rows x 16 k), float4 loads, transposed store
#pragma unroll
        for (int q = 0; q < 4; q++) {
            int idx = threadIdx.x + q * 256;      // 0..1023 float4s
            int rr = idx >> 2;
            int kq = (idx & 3) * 4;
            int gr = r0 + rr;
            float4 v = (gr < Rtot) ? *(const float4*)&W[(size_t)gr * lda + kc + kq]
                                   : make_float4(0.f, 0.f, 0.f, 0.f);
            sWT[kq + 0][rr] = v.x; sWT[kq + 1][rr] = v.y;
            sWT[kq + 2][rr] = v.z; sWT[kq + 3][rr] = v.w;
        }
        // stage E tile (64 b x 16 k)
        {
            int bb = threadIdx.x >> 2;
            int kq = (threadIdx.x & 3) * 4;
            float4 v = *(const float4*)&E[bb * ldE + kc + kq];
            sE[kq + 0][bb] = v.x; sE[kq + 1][bb] = v.y;
            sE[kq + 2][bb] = v.z; sE[kq + 3][bb] = v.w;
        }
        __syncthreads();
#pragma unroll
        for (int kk = 0; kk < KC; kk++) {
            float a[8];
            *(float4*)&a[0] = *(const float4*)&sWT[kk][trow * 8];
            *(float4*)&a[4] = *(const float4*)&sWT[kk][trow * 8 + 4];
            ulonglong2 q0 = *(const ulonglong2*)&sE[kk][tcol * 8];
            ulonglong2 q1 = *(const ulonglong2*)&sE[kk][tcol * 8 + 4];
            unsigned long long b2[4] = {q0.x, q0.y, q1.x, q1.y};
#pragma unroll
            for (int i = 0; i < 8; i++) {
                unsigned long long ua = pack2(a[i], a[i]);
#pragma unroll
                for (int j = 0; j < 4; j++) fma2(acc2[i][j], ua, b2[j]);
            }
        }
        __syncthreads();
    }
#pragma unroll
    for (int i = 0; i < 8; i++) {
        int gr = r0 + trow * 8 + i;
        if (gr < Rtot) {
#pragma unroll
            for (int j = 0; j < 4; j++) {
                float2 v = unpack2(acc2[i][j]);
                atomicAdd(&C[(size_t)(tcol * 8 + 2 * j) * ldC + gr], v.x);
                atomicAdd(&C[(size_t)(tcol * 8 + 2 * j + 1) * ldC + gr], v.y);
            }
        }
    }
}

// ---------------- persistent GRU recurrence: weights in registers ----------------
__global__ void __launch_bounds__(256) k_gru(const float* __restrict__ W_hh,
                                             const float* __restrict__ b_hh,
                                             float* __restrict__ out)
{
    __shared__ float sH[H_];
    const int t = threadIdx.x, w = t >> 5, lane = t & 31;
    const int j = blockIdx.x * 8 + w;

    // this warp's three weight rows, register-resident (96 floats/lane)
    float4 wr[8], wz[8], wn[8];
    const float4* Wr4 = (const float4*)(W_hh + (size_t)j * H_);
    const float4* Wz4 = (const float4*)(W_hh + (size_t)(H_ + j) * H_);
    const float4* Wn4 = (const float4*)(W_hh + (size_t)(2 * H_ + j) * H_);
#pragma unroll
    for (int i = 0; i < 8; i++) {
        wr[i] = Wr4[lane + i * 32];
        wz[i] = Wz4[lane + i * 32];
        wn[i] = Wn4[lane + i * 32];
    }
    const float bhr = b_hh[j], bhz = b_hh[H_ + j], bhn = b_hh[2 * H_ + j];
    const unsigned nb = gridDim.x;
    const float4* sH4 = (const float4*)sH;

    for (int b = 0; b < B_; b++) {
        // stage h (bypass L1; written by other SMs)
        {
            const float4* hsrc = (const float4*)(g_h + (b & 1) * H_);
            ((float4*)sH)[t] = __ldcg(hsrc + t);
        }
        __syncthreads();

        const float* gib = g_gi + b * 3 * H_;
        float gir = gib[j], giz = gib[H_ + j], gin = gib[2 * H_ + j];

        float ar = 0.f, az = 0.f, an = 0.f;
#pragma unroll
        for (int i = 0; i < 8; i++) {
            float4 h4 = sH4[lane + i * 32];
            ar = fmaf(wr[i].x, h4.x, ar); az = fmaf(wz[i].x, h4.x, az); an = fmaf(wn[i].x, h4.x, an);
            ar = fmaf(wr[i].y, h4.y, ar); az = fmaf(wz[i].y, h4.y, az); an = fmaf(wn[i].y, h4.y, an);
            ar = fmaf(wr[i].z, h4.z, ar); az = fmaf(wz[i].z, h4.z, az); an = fmaf(wn[i].z, h4.z, an);
            ar = fmaf(wr[i].w, h4.w, ar); az = fmaf(wz[i].w, h4.w, az); an = fmaf(wn[i].w, h4.w, an);
        }
#pragma unroll
        for (int off = 16; off; off >>= 1) {
            ar += __shfl_down_sync(0xffffffffu, ar, off);
            az += __shfl_down_sync(0xffffffffu, az, off);
            an += __shfl_down_sync(0xffffffffu, an, off);
        }
        if (lane == 0) {
            float r = 1.f / (1.f + expf(-(gir + ar + bhr)));
            float z = 1.f / (1.f + expf(-(giz + az + bhz)));
            float n = tanhf(gin + r * (an + bhn));
            float hp = sH[j];
            float hn = (1.f - z) * n + z * hp;
            g_h[((b + 1) & 1) * H_ + j] = hn;
            g_cat[b * 2 * H_ + j] = hn;
            if (b == B_ - 1) out[B_ * V_ + j] = hn;   // hidden output
            __threadfence();                           // publish before arrival
        }
        __syncthreads();
        if (t == 0) {
            atomicAdd(&g_bar, 1u);
            unsigned target = (unsigned)(b + 1) * nb;
            volatile unsigned* vb = &g_bar;
            while (*vb < target) { }
            __threadfence();                           // acquire
        }
        __syncthreads();
    }
}

// ---------------- attention scores: scores[b][s] = enc[s][b][:] . u_e ----------------
__global__ void __launch_bounds__(256) k_scores(const float* __restrict__ enc)
{
    __shared__ float su[H_];
    for (int i = threadIdx.x; i < H_; i += 256) su[i] = g_ue[i];
    __syncthreads();
    int w = threadIdx.x >> 5, lane = threadIdx.x & 31;
    int gw = blockIdx.x * 8 + w;      // 0..16383
    int b = gw >> 8, s = gw & 255;
    const float4* p = (const float4*)(enc + (size_t)s * (B_ * H_) + b * H_);
    const float4* su4 = (const float4*)su;
    float acc = 0.f;
#pragma unroll
    for (int i = 0; i < 8; i++) {
        float4 x = p[lane + i * 32];
        float4 u = su4[lane + i * 32];
        acc = fmaf(x.x, u.x, acc);
        acc = fmaf(x.y, u.y, acc);
        acc = fmaf(x.z, u.z, acc);
        acc = fmaf(x.w, u.w, acc);
    }
#pragma unroll
    for (int off = 16; off; off >>= 1) acc += __shfl_down_sync(0xffffffffu, acc, off);
    if (lane == 0) g_scores[b * S_ + s] = acc;
}

// ---------------- softmax over s (per b) ----------------
__global__ void __launch_bounds__(256) k_softmax(float* __restrict__ out)
{
    int b = blockIdx.x, t = threadIdx.x;
    float v = g_scores[b * S_ + t];
    __shared__ float red[256];
    red[t] = v; __syncthreads();
    for (int o = 128; o; o >>= 1) { if (t < o) red[t] = fmaxf(red[t], red[t + o]); __syncthreads(); }
    float m = red[0]; __syncthreads();
    float e = expf(v - m);
    red[t] = e; __syncthreads();
    for (int o = 128; o; o >>= 1) { if (t < o) red[t] += red[t + o]; __syncthreads(); }
    float wgt = e / red[0];
    g_scores[b * S_ + t] = wgt;
    out[B_ * V_ + H_ + b * S_ + t] = wgt;   // attn_weights output
}

// ---------------- context: ctx[b][h] = sum_s w[b][s] * enc[s][b][h] ----------------
__global__ void __launch_bounds__(256) k_context(const float* __restrict__ enc)
{
    int b = blockIdx.x >> 2;
    int hb = (blockIdx.x & 3) * 256;
    __shared__ float sw_[S_];
    sw_[threadIdx.x] = g_scores[b * S_ + threadIdx.x];
    __syncthreads();
    int h = hb + threadIdx.x;
    const float* p = enc + b * H_ + h;
    float a0 = 0.f, a1 = 0.f, a2 = 0.f, a3 = 0.f;
#pragma unroll 4
    for (int s = 0; s < S_; s += 4) {
        a0 = fmaf(sw_[s + 0], p[(size_t)(s + 0) * (B_ * H_)], a0);
        a1 = fmaf(sw_[s + 1], p[(size_t)(s + 1) * (B_ * H_)], a1);
        a2 = fmaf(sw_[s + 2], p[(size_t)(s + 2) * (B_ * H_)], a2);
        a3 = fmaf(sw_[s + 3], p[(size_t)(s + 3) * (B_ * H_)], a3);
    }
    g_cat[b * 2 * H_ + H_ + h] = (a0 + a1) + (a2 + a3);
}

// ---------------- tanh staging: g_E = tanh(g_pre), computed once ----------------
__global__ void __launch_bounds__(256) k_tanh()
{
    int idx = blockIdx.x * 256 + threadIdx.x;     // 16384 float4s
    float4 v = ((const float4*)g_pre)[idx];
    v.x = tanhf(v.x); v.y = tanhf(v.y); v.z = tanhf(v.z); v.w = tanhf(v.w);
    ((float4*)g_E)[idx] = v;
}

extern "C" void kernel_launch(void* const* d_in, const int* in_sizes, int n_in,
                              void* d_out, int out_size)
{
    const int*   seq         = (const int*)d_in[0];
    const float* last_hidden = (const float*)d_in[1];
    const float* enc         = (const float*)d_in[2];
    const float* emb_table   = (const float*)d_in[3];
    const float* W_ih        = (const float*)d_in[4];
    const float* W_hh        = (const float*)d_in[5];
    const float* b_ih        = (const float*)d_in[6];
    const float* b_hh        = (const float*)d_in[7];
    const float* W_attn      = (const float*)d_in[8];
    /* d_in[9] = b_attn: dropped — softmax is shift-invariant */
    const float* v_attn      = (const float*)d_in[10];
    const float* W_concat    = (const float*)d_in[11];
    const float* b_concat    = (const float*)d_in[12];
    const float* W_out       = (const float*)d_in[13];
    const float* b_out       = (const float*)d_in[14];
    float* out = (float*)d_out;

    // init + embedding + h0 + barrier reset
    k_pre<<<65, 256>>>(seq, last_hidden, emb_table, b_ih, b_concat, b_out, out);

    // u_e for collapsed attention
    k_ue<<<64, 256>>>(W_attn, v_attn);

    // gi = emb @ W_ih^T (+b_ih pre-init): 12 row-blocks x splitK 8
    k_gemm<0><<<dim3(12, 8), 256>>>(W_ih, H_, 3 * H_, 128, nullptr);

    // attention (independent of GRU): scores -> softmax -> context
    k_scores<<<2048, 256>>>(enc);
    k_softmax<<<64, 256>>>(out);
    k_context<<<256, 256>>>(enc);

    // sequential GRU recurrence (persistent grid, register-resident weights)
    k_gru<<<GRU_BLOCKS, 256>>>(W_hh, b_hh, out);

    // concat preactivation: g_pre += [rnn|ctx] @ W_concat^T: 4 row-blocks x splitK 16
    k_gemm<1><<<dim3(4, 16), 256>>>(W_concat, 2 * H_, H_, 128, nullptr);

    // tanh once
    k_tanh<<<64, 256>>>();

    // logits: out += g_E @ W_out^T: 40 row-blocks x splitK 4
    k_gemm<2><<<dim3(40, 4), 256>>>(W_out, H_, V_, 256, out);
}